// round 3
// baseline (speedup 1.0000x reference)
#include <cuda_runtime.h>

#define WSZ 21
#define KW  43
#define IH  128
#define IW  128
#define IB  2
#define NPIX (IB*IH*IW)   // 32768

// scratch (__device__ globals: no allocation allowed)
__device__ float4 g_s4[NPIX];
__device__ float4 g_o4[NPIX];
__device__ float  g_mask[NPIX];
__device__ float  g_swtab[KW];
__device__ double g_partial[256];

__device__ __forceinline__ float ex2f(float x) {
    float y;
    asm("ex2.approx.ftz.f32 %0, %1;" : "=f"(y) : "f"(x));
    return y;
}
__device__ __forceinline__ float lg2f(float x) {
    float y;
    asm("lg2.approx.ftz.f32 %0, %1;" : "=f"(y) : "f"(x));
    return y;
}

__device__ __forceinline__ int refl(int p, int n) {
    if (p < 0) p = -p;
    if (p >= n) p = 2*n - 2 - p;
    return p;
}

// Pack channels into float4, compute Sobel edge masks, spatial table, zero partials.
__global__ void prep_kernel(const float* __restrict__ orig, const float* __restrict__ smo) {
    int idx = blockIdx.x * blockDim.x + threadIdx.x;
    if (idx < 256) g_partial[idx] = 0.0;
    if (idx < KW) {
        float d = (float)(idx - WSZ);
        g_swtab[idx] = expf(-(1.0f/98.0f) * d * d);   // SIGMA_SPACE = 1/(2*49)
    }
    if (idx >= NPIX) return;
    int c = idx & (IW-1);
    int r = (idx >> 7) & (IH-1);
    int b = idx >> 14;
    const float* ob = orig + b*3*IH*IW;
    const float* sb = smo  + b*3*IH*IW;
    int rm = refl(r-1, IH), rp = refl(r+1, IH);
    int cm = refl(c-1, IW), cp = refl(c+1, IW);
    float eo = 0.f, es = 0.f;
    float oo[3], ss[3];
    #pragma unroll
    for (int ch = 0; ch < 3; ++ch) {
        const float* p = ob + ch*IH*IW;
        float a00=p[rm*IW+cm], a01=p[rm*IW+c], a02=p[rm*IW+cp];
        float a10=p[r *IW+cm], a11=p[r *IW+c], a12=p[r *IW+cp];
        float a20=p[rp*IW+cm], a21=p[rp*IW+c], a22=p[rp*IW+cp];
        float gx = (a02 + 2.f*a12 + a22) - (a00 + 2.f*a10 + a20);
        float gy = (a20 + 2.f*a21 + a22) - (a00 + 2.f*a01 + a02);
        eo += sqrtf(gx*gx + gy*gy);
        oo[ch] = a11;
        const float* q = sb + ch*IH*IW;
        float b00=q[rm*IW+cm], b01=q[rm*IW+c], b02=q[rm*IW+cp];
        float b10=q[r *IW+cm], b11=q[r *IW+c], b12=q[r *IW+cp];
        float b20=q[rp*IW+cm], b21=q[rp*IW+c], b22=q[rp*IW+cp];
        float hx = (b02 + 2.f*b12 + b22) - (b00 + 2.f*b10 + b20);
        float hy = (b20 + 2.f*b21 + b22) - (b00 + 2.f*b01 + b02);
        es += sqrtf(hx*hx + hy*hy);
        ss[ch] = b11;
    }
    g_mask[idx] = ((eo < 20.f) && (es - eo > 10.f)) ? 1.f : 0.f;
    g_s4[idx] = make_float4(ss[0], ss[1], ss[2], 0.f);
    g_o4[idx] = make_float4(oo[0], oo[1], oo[2], 0.f);
}

// One block per (batch*row, x-offset). 128 threads = one per column.
// Each thread loops the 43 y-offsets reading a shared padded row.
__global__ void __launch_bounds__(128) main_kernel() {
    __shared__ float4 sS[IW + 2*WSZ];   // 170
    __shared__ float4 sO[IW + 2*WSZ];
    __shared__ float  swy[KW];
    __shared__ float  wpart[4];

    int t  = threadIdx.x;
    int bx = blockIdx.x;
    int xo = bx % KW - WSZ;      // x-offset in [-21,21]
    int rg = bx / KW;            // 0..255 = batch*row
    int b  = rg >> 7;
    int r  = rg & (IH-1);

    int srow = refl(r + xo, IH);
    int base = b*IH*IW + srow*IW;
    for (int j = t; j < IW + 2*WSZ; j += 128) {
        int cj = refl(j - WSZ, IW);
        sS[j] = g_s4[base + cj];
        sO[j] = g_o4[base + cj];
    }
    if (t < KW) swy[t] = g_swtab[t];
    __syncthreads();

    int cidx = b*IH*IW + r*IW + t;
    float4 sc = g_s4[cidx];
    float4 oc = g_o4[cidx];
    float mL = g_mask[cidx];
    float mS = 1.f - mL;
    float aL = mL * g_swtab[xo + WSZ];   // m_large * exp(-sigma*x^2)

    float acc = 0.f;
    #pragma unroll 4
    for (int j = 0; j < KW; ++j) {
        float4 s = sS[t + j];
        float4 o = sO[t + j];
        float d0 = fabsf(sc.x - s.x);
        float d1 = fabsf(sc.y - s.y);
        float d2 = fabsf(sc.z - s.z);
        float dd = d0*d0 + d1*d1 + d2*d2;
        float u0 = oc.x - o.x, u1 = oc.y - o.y, u2 = oc.z - o.z;
        float rr = u0*u0 + u1*u1 + u2*u2;
        // exp(-50*rr) = exp2(-50*log2(e)*rr)
        float wr = ex2f(-72.13475204444817f * rr);
        // d^0.8 = exp2(0.8*log2(d)); lg2(0) = -inf -> ex2 -> 0 (matches safe_pow)
        float p0 = ex2f(0.8f * lg2f(d0));
        float p1 = ex2f(0.8f * lg2f(d1));
        float p2 = ex2f(0.8f * lg2f(d2));
        acc += aL * swy[j] * dd + mS * wr * (p0 + p1 + p2);
    }

    // warp reduce
    #pragma unroll
    for (int off = 16; off; off >>= 1)
        acc += __shfl_xor_sync(0xffffffffu, acc, off);
    if ((t & 31) == 0) wpart[t >> 5] = acc;
    __syncthreads();
    if (t == 0) {
        float bs = wpart[0] + wpart[1] + wpart[2] + wpart[3];
        atomicAdd(&g_partial[bx & 255], (double)bs);
    }
}

__global__ void finalize_kernel(float* __restrict__ out) {
    __shared__ double sh[256];
    int t = threadIdx.x;
    sh[t] = g_partial[t];
    __syncthreads();
    for (int s = 128; s > 0; s >>= 1) {
        if (t < s) sh[t] += sh[t + s];
        __syncthreads();
    }
    if (t == 0) out[0] = (float)(sh[0] / (double)NPIX);
}

extern "C" void kernel_launch(void* const* d_in, const int* in_sizes, int n_in,
                              void* d_out, int out_size) {
    const float* orig = (const float*)d_in[0];
    const float* smo  = (const float*)d_in[1];
    float* out = (float*)d_out;
    (void)in_sizes; (void)n_in; (void)out_size;

    prep_kernel<<<(NPIX + 255)/256, 256>>>(orig, smo);
    main_kernel<<<IB*IH*KW, 128>>>();       // 11008 blocks
    finalize_kernel<<<1, 256>>>(out);
}